// round 4
// baseline (speedup 1.0000x reference)
#include <cuda_runtime.h>
#include <cuda_bf16.h>
#include <math.h>

#define N_TOK 2048
#define NROWS 16384   // GEMM M (token, codebook-group) rows
#define KCB   16384   // GEMM N (codebook entries)

// ---------------- persistent scratch (no allocs allowed) ----------------
__device__ float g_At[64 * NROWS];    // fp32 features [f][n] (rescue): f<32 -> 0.5*(1-inv_var), f>=32 -> mu*inv_var
__device__ float g_CBt[64 * KCB];     // fp32 features [f][k] (rescue): f<32 -> c^2, f>=32 -> c
__device__ __align__(16) __nv_bfloat16 g_Asp[NROWS * 128];  // 2-split [n][s*64+f]
__device__ __align__(16) __nv_bfloat16 g_Bsp[KCB * 128];    // 2-split [k][s*64+f]
__device__ float g_klpart[N_TOK];
__device__ int   g_idx[NROWS];
__device__ int   g_flag[NROWS];

// ---------------------------------------------------------------- prep
__global__ void prep_kernel(const float* __restrict__ z) {
    int t = blockIdx.x;       // 2048 tokens
    int j = threadIdx.x;      // 256 features
    float mu = z[t * 512 + j];
    float lv = z[t * 512 + 256 + j];
    lv = fminf(fmaxf(lv, -30.0f), 20.0f);
    float var = expf(lv);
    float inv_var = 1.0f / var;
    int d = j >> 3, c = j & 7;
    int n = t * 8 + c;
    g_At[d * NROWS + n]        = 0.5f * (1.0f - inv_var);
    g_At[(d + 32) * NROWS + n] = mu * inv_var;

    float e = mu * mu + var - 1.0f - lv;   // kl partial (band coeffs sum to 1)
    __shared__ float red[256];
    red[j] = e;
    __syncthreads();
    for (int s = 128; s > 0; s >>= 1) {
        if (j < s) red[j] += red[j + s];
        __syncthreads();
    }
    if (j == 0) g_klpart[t] = red[0];
}

__global__ void cb_kernel(const float* __restrict__ cb) {
    int i = blockIdx.x * 256 + threadIdx.x;   // 524288
    if (i >= KCB * 32) return;
    int k = i >> 5, d = i & 31;
    float v = cb[i];
    g_CBt[d * KCB + k]        = v * v;
    g_CBt[(d + 32) * KCB + k] = v;
}

// 2-way bf16 residual split
__global__ void asplit_kernel() {
    int i = blockIdx.x * 256 + threadIdx.x;   // 16384*64
    int n = i >> 6, f = i & 63;
    float v = g_At[f * NROWS + n];
    __nv_bfloat16 x1 = __float2bfloat16(v);
    float r1 = v - __bfloat162float(x1);
    g_Asp[n * 128 + f]      = x1;
    g_Asp[n * 128 + 64 + f] = __float2bfloat16(r1);
}
__global__ void bsplit_kernel() {
    int i = blockIdx.x * 256 + threadIdx.x;   // 16384*64
    int k = i >> 6, f = i & 63;
    float v = g_CBt[f * KCB + k];
    __nv_bfloat16 x1 = __float2bfloat16(v);
    float r1 = v - __bfloat162float(x1);
    g_Bsp[k * 128 + f]      = x1;
    g_Bsp[k * 128 + 64 + f] = __float2bfloat16(r1);
}

// ---------------------------------------------------------------- PTX helpers (sm_80-era only!)
__device__ __forceinline__ void cp16(unsigned dst, const void* src) {
    asm volatile("cp.async.cg.shared.global [%0], [%1], 16;\n" :: "r"(dst), "l"(src));
}
__device__ __forceinline__ void ldsm4(unsigned* d, unsigned addr) {
    asm volatile("ldmatrix.sync.aligned.m8n8.x4.shared.b16 {%0,%1,%2,%3}, [%4];"
                 : "=r"(d[0]), "=r"(d[1]), "=r"(d[2]), "=r"(d[3]) : "r"(addr));
}
__device__ __forceinline__ void mma16816(float* c, const unsigned* a, unsigned b0, unsigned b1) {
    asm volatile(
        "mma.sync.aligned.m16n8k16.row.col.f32.bf16.bf16.f32 "
        "{%0,%1,%2,%3}, {%4,%5,%6,%7}, {%8,%9}, {%0,%1,%2,%3};"
        : "+f"(c[0]), "+f"(c[1]), "+f"(c[2]), "+f"(c[3])
        : "r"(a[0]), "r"(a[1]), "r"(a[2]), "r"(a[3]), "r"(b0), "r"(b1));
}

// ---------------------------------------------------------------- VQ GEMM + fused argmax
// grid 128. CTA: M-tile 128 rows, loops 128 N-tiles of 128. K: 2-split, 3 term-pairs = 12 k16 steps.
// smem: sA 32KB persistent + sB 2x32KB double buffer. XOR-swizzled 16B chunks for ldmatrix.
#define SB_OFF 32768
#define SMEM_SZ 98304

__global__ __launch_bounds__(256, 1) void vq_mma_kernel() {
    extern __shared__ char smem[];
    unsigned s_u32 = (unsigned)__cvta_generic_to_shared(smem);
    int tid = threadIdx.x;
    int lane = tid & 31, w = tid >> 5;
    int wm = w >> 2, wn = w & 3;           // 2 x 4 warp grid (64 x 32 warp tiles)
    int l15 = lane & 15, lhi = lane >> 4;
    int n0 = blockIdx.x * 128;

    // ---- prefetch B tile 0 ----
    {
        const __nv_bfloat16* src = g_Bsp;
#pragma unroll
        for (int t = 0; t < 8; t++) {
            int ch = tid + t * 256;        // 2048 chunks of 16B
            int r = ch >> 4, c = ch & 15;
            cp16(s_u32 + SB_OFF + r * 256 + ((c ^ (r & 7)) << 4), src + r * 128 + c * 8);
        }
        asm volatile("cp.async.commit_group;\n" ::: "memory");
    }

    // ---- load A tile (128 rows x 128 bf16), swizzled ----
#pragma unroll
    for (int t = 0; t < 8; t++) {
        int ch = tid + t * 256;
        int r = ch >> 4, c = ch & 15;
        uint4 v = *(const uint4*)(g_Asp + (size_t)(n0 + r) * 128 + c * 8);
        *(uint4*)(smem + r * 256 + ((c ^ (r & 7)) << 4)) = v;
    }

    // per-thread ldmatrix base addresses
    unsigned aBase[4], aXor[4];
#pragma unroll
    for (int mi = 0; mi < 4; mi++) {
        int r = wm * 64 + mi * 16 + l15;
        aBase[mi] = s_u32 + r * 256;
        aXor[mi] = (unsigned)(r & 7);
    }
    unsigned bBase[2], bXor[2];
#pragma unroll
    for (int p = 0; p < 2; p++) {
        int r = wn * 32 + p * 16 + l15;
        bBase[p] = s_u32 + SB_OFF + r * 256;
        bXor[p] = (unsigned)(r & 7);
    }

    float mx[8], m2[8];
    int bi[8];
#pragma unroll
    for (int s = 0; s < 8; s++) { mx[s] = -INFINITY; m2[s] = -INFINITY; bi[s] = 0; }

    for (int j = 0; j < 128; j++) {
        if (j + 1 < 128) {
            const __nv_bfloat16* src = g_Bsp + (size_t)(j + 1) * 128 * 128;
            unsigned dst = s_u32 + SB_OFF + ((j + 1) & 1) * SB_OFF;
#pragma unroll
            for (int t = 0; t < 8; t++) {
                int ch = tid + t * 256;
                int r = ch >> 4, c = ch & 15;
                cp16(dst + r * 256 + ((c ^ (r & 7)) << 4), src + r * 128 + c * 8);
            }
            asm volatile("cp.async.commit_group;\n" ::: "memory");
            asm volatile("cp.async.wait_group 1;\n" ::: "memory");
        } else {
            asm volatile("cp.async.wait_group 0;\n" ::: "memory");
        }
        __syncthreads();

        unsigned bufoff = (unsigned)((j & 1) * SB_OFF);

        float C[4][4][4];
#pragma unroll
        for (int mi = 0; mi < 4; mi++)
#pragma unroll
            for (int ni = 0; ni < 4; ni++)
#pragma unroll
                for (int r = 0; r < 4; r++) C[mi][ni][r] = 0.0f;

        // 12 k16 steps: terms (a1,b1), (a1,b2), (a2,b1)
        const int ASEL[3] = {0, 0, 1};
        const int BSEL[3] = {0, 1, 0};
#pragma unroll
        for (int s = 0; s < 12; s++) {
            const int term = s >> 2, kk = s & 3;
            const int ak = ASEL[term] * 64 + kk * 16;
            const int bk = BSEL[term] * 64 + kk * 16;
            unsigned af[4][4], bf[2][4];
            unsigned ca = (unsigned)((ak >> 3) + lhi);
            unsigned cbk = (unsigned)((bk >> 3) + lhi);
#pragma unroll
            for (int mi = 0; mi < 4; mi++)
                ldsm4(af[mi], aBase[mi] + ((ca ^ aXor[mi]) << 4));
#pragma unroll
            for (int p = 0; p < 2; p++)
                ldsm4(bf[p], bBase[p] + bufoff + ((cbk ^ bXor[p]) << 4));
#pragma unroll
            for (int mi = 0; mi < 4; mi++)
#pragma unroll
                for (int ni = 0; ni < 4; ni++)
                    mma16816(C[mi][ni], af[mi], bf[ni >> 1][ni & 1], bf[ni >> 1][(ni & 1) + 2]);
        }

        // fused in-register argmax (track max + second max)
        int colbase = j * 128 + wn * 32 + (lane & 3) * 2;
#pragma unroll
        for (int mi = 0; mi < 4; mi++)
#pragma unroll
            for (int h = 0; h < 2; h++) {
                int slot = mi * 2 + h;
#pragma unroll
                for (int ni = 0; ni < 4; ni++)
#pragma unroll
                    for (int q = 0; q < 2; q++) {
                        float v = C[mi][ni][h * 2 + q];
                        int col = colbase + ni * 8 + q;
                        if (v > mx[slot]) { m2[slot] = mx[slot]; mx[slot] = v; bi[slot] = col; }
                        else if (v > m2[slot]) { m2[slot] = v; }
                    }
            }
        __syncthreads();
    }

    // ---- reduce across the 4 lanes sharing each row ----
#pragma unroll
    for (int slot = 0; slot < 8; slot++) {
        float a_mx = mx[slot], a_m2 = m2[slot];
        int a_bi = bi[slot];
#pragma unroll
        for (int off = 1; off <= 2; off <<= 1) {
            float o_mx = __shfl_xor_sync(0xffffffffu, a_mx, off);
            float o_m2 = __shfl_xor_sync(0xffffffffu, a_m2, off);
            int   o_bi = __shfl_xor_sync(0xffffffffu, a_bi, off);
            float n_m2 = fmaxf(fminf(a_mx, o_mx), fmaxf(a_m2, o_m2));
            if (o_mx > a_mx || (o_mx == a_mx && o_bi < a_bi)) { a_mx = o_mx; a_bi = o_bi; }
            a_m2 = n_m2;
        }
        mx[slot] = a_mx; m2[slot] = a_m2; bi[slot] = a_bi;
    }

    // ---- cross-warp reduce (4 n-warps share rows) via smem overlay on sA ----
    float* redMx = (float*)smem;           // [128][4]
    float* redM2 = (float*)smem + 512;     // [128][4]
    int*   redBi = (int*)smem + 1024;      // [128][4]
    __syncthreads();
    if ((lane & 3) == 0) {
#pragma unroll
        for (int slot = 0; slot < 8; slot++) {
            int mi = slot >> 1, h = slot & 1;
            int row = wm * 64 + mi * 16 + (lane >> 2) + 8 * h;
            redMx[row * 4 + wn] = mx[slot];
            redM2[row * 4 + wn] = m2[slot];
            redBi[row * 4 + wn] = bi[slot];
        }
    }
    __syncthreads();
    if (tid < 128) {
        float a_mx = redMx[tid * 4], a_m2 = redM2[tid * 4];
        int a_bi = redBi[tid * 4];
#pragma unroll
        for (int q = 1; q < 4; q++) {
            float o_mx = redMx[tid * 4 + q], o_m2 = redM2[tid * 4 + q];
            int o_bi = redBi[tid * 4 + q];
            float n_m2 = fmaxf(fminf(a_mx, o_mx), fmaxf(a_m2, o_m2));
            if (o_mx > a_mx || (o_mx == a_mx && o_bi < a_bi)) { a_mx = o_mx; a_bi = o_bi; }
            a_m2 = n_m2;
        }
        int n = n0 + tid;
        g_idx[n] = a_bi;
        g_flag[n] = (a_mx - a_m2 < 0.1f + 2e-3f * fabsf(a_mx)) ? 1 : 0;
    }
}

// ---------------------------------------------------------------- exact fp32 rescue for near-ties
__global__ void rescue_kernel() {
    int n = blockIdx.x;
    if (!g_flag[n]) return;
    __shared__ float sa[64];
    __shared__ float rm[128];
    __shared__ int   ri[128];
    int tid = threadIdx.x;
    if (tid < 64) sa[tid] = g_At[tid * NROWS + n];
    __syncthreads();
    float mx = -INFINITY; int bi = KCB;
    for (int k = tid; k < KCB; k += 128) {
        float s = 0.0f;
#pragma unroll
        for (int f = 0; f < 64; f++) s += sa[f] * g_CBt[f * KCB + k];
        if (s > mx) { mx = s; bi = k; }
    }
    rm[tid] = mx; ri[tid] = bi;
    __syncthreads();
    for (int st = 64; st > 0; st >>= 1) {
        if (tid < st) {
            if (rm[tid + st] > rm[tid] || (rm[tid + st] == rm[tid] && ri[tid + st] < ri[tid])) {
                rm[tid] = rm[tid + st]; ri[tid] = ri[tid + st];
            }
        }
        __syncthreads();
    }
    if (tid == 0) g_idx[n] = ri[0];
}

// ---------------------------------------------------------------- outputs
__global__ void gather_kernel(const float* __restrict__ cb, float* __restrict__ out) {
    int i = blockIdx.x * 256 + threadIdx.x;   // 524288 zhat elements
    if (i >= N_TOK * 256) return;
    int j = i & 255;
    int t = i >> 8;
    int idx = g_idx[t * 8 + (j & 7)];
    out[i] = cb[idx * 32 + (j >> 3)];          // zhat[t, d*8+c] = codebook[idx[t,c], d]
}

__global__ void final_small(float* __restrict__ out) {
    if (blockIdx.x == 0) {
        __shared__ float red[256];
        int j = threadIdx.x;
        float s = 0.0f;
        for (int i = j; i < N_TOK; i += 256) s += g_klpart[i];
        red[j] = s;
        __syncthreads();
        for (int st = 128; st > 0; st >>= 1) {
            if (j < st) red[j] += red[j + st];
            __syncthreads();
        }
        if (j == 0) out[524288] = red[0] * (1.4426f * 0.5f) / 16384.0f;
    } else {
        int i = (blockIdx.x - 1) * 256 + threadIdx.x;
        if (i < NROWS) out[524289 + i] = (float)g_idx[i];
    }
}

// ---------------------------------------------------------------- launch
extern "C" void kernel_launch(void* const* d_in, const int* in_sizes, int n_in,
                              void* d_out, int out_size) {
    const float* z  = (const float*)d_in[0];
    // d_in[1] (noise) is mathematically dead: forward zhat == codebook gather
    const float* cb = (const float*)d_in[2];
    float* out = (float*)d_out;

    cudaFuncSetAttribute(vq_mma_kernel, cudaFuncAttributeMaxDynamicSharedMemorySize, SMEM_SZ);

    prep_kernel<<<2048, 256>>>(z);
    cb_kernel<<<2048, 256>>>(cb);
    asplit_kernel<<<4096, 256>>>();
    bsplit_kernel<<<4096, 256>>>();
    vq_mma_kernel<<<128, 256, SMEM_SZ>>>();
    rescue_kernel<<<KCB, 128>>>();
    gather_kernel<<<2048, 256>>>(cb, out);
    final_small<<<65, 256>>>(out);
}

// round 5
// speedup vs baseline: 1.9187x; 1.9187x over previous
#include <cuda_runtime.h>
#include <math.h>

#define N_TOK 2048
#define NROWS 16384   // GEMM M rows (token, codebook-group)
#define KCB   16384   // codebook entries
#define NCTA  148     // one CTA per SM, balanced row ranges

// ---------------- persistent scratch (no allocs allowed) ----------------
__device__ float g_At[64 * NROWS];   // [f][n]: f<32 -> 0.5*(1-inv_var), f>=32 -> mu*inv_var
__device__ float g_CBt[64 * KCB];    // [f][k]: f<32 -> c^2, f>=32 -> c
__device__ float g_klpart[N_TOK];
__device__ int   g_idx[NROWS];

// ---------------------------------------------------------------- prep
__global__ void prep_kernel(const float* __restrict__ z) {
    int t = blockIdx.x;       // 2048 tokens
    int j = threadIdx.x;      // 256 features
    float mu = z[t * 512 + j];
    float lv = z[t * 512 + 256 + j];
    lv = fminf(fmaxf(lv, -30.0f), 20.0f);
    float var = expf(lv);
    float inv_var = 1.0f / var;
    int d = j >> 3, c = j & 7;
    int n = t * 8 + c;
    g_At[d * NROWS + n]        = 0.5f * (1.0f - inv_var);
    g_At[(d + 32) * NROWS + n] = mu * inv_var;

    float e = mu * mu + var - 1.0f - lv;   // kl partial (band coeffs sum to 1)
    __shared__ float red[256];
    red[j] = e;
    __syncthreads();
    for (int s = 128; s > 0; s >>= 1) {
        if (j < s) red[j] += red[j + s];
        __syncthreads();
    }
    if (j == 0) g_klpart[t] = red[0];
}

__global__ void cb_kernel(const float* __restrict__ cb) {
    int i = blockIdx.x * 256 + threadIdx.x;   // 524288
    if (i >= KCB * 32) return;
    int k = i >> 5, d = i & 31;
    float v = cb[i];
    g_CBt[d * KCB + k]        = v * v;
    g_CBt[(d + 32) * KCB + k] = v;
}

// ---------------------------------------------------------------- GEMM + argmax
__device__ __forceinline__ void cp16(unsigned dst, const void* src) {
    asm volatile("cp.async.cg.shared.global [%0], [%1], 16;\n" :: "r"(dst), "l"(src));
}
__device__ __forceinline__ void fma2(unsigned long long& d, unsigned long long a, unsigned long long b) {
    asm("fma.rn.f32x2 %0, %1, %2, %3;" : "=l"(d) : "l"(a), "l"(b), "l"(d));
}

// 148 CTAs x 256 threads (16x16). Each CTA owns rows [bid*16384/148, (bid+1)*16384/148)
// (110-111 rows), computes a padded 112-row tile: 7 rows/thread, BK=128 codebook
// entries per tile, 8 cols/thread as 4 f32x2 accumulators. A duplicated in smem so
// one LDS.128 yields two broadcast-ready (a,a) f32x2 operands.
__global__ __launch_bounds__(256, 1) void vq_kernel() {
    extern __shared__ float smem[];
    float* sA = smem;             // [64][256]: 16 ty-groups x (7 dup pairs + 2 pad floats)
    float* sB = smem + 64 * 256;  // [2][64][128] double-buffered
    int tid = threadIdx.x;
    int tx = tid & 15, ty = tid >> 4;
    int bid = blockIdx.x;
    int base = (int)(((long long)bid * NROWS) / NCTA);
    int cnt  = (int)(((long long)(bid + 1) * NROWS) / NCTA) - base;   // 110 or 111
    unsigned sB_base = (unsigned)__cvta_generic_to_shared(sB);

    // Load + duplicate A tile (112 rows, clamped reads for the pad rows)
    for (int i = tid; i < 64 * 112; i += 256) {
        int d = i / 112, r = i % 112;
        int n = base + r; if (n > NROWS - 1) n = NROWS - 1;
        float v = g_At[d * NROWS + n];
        int g = r / 7, p = r % 7;
        sA[d * 256 + g * 16 + 2 * p]     = v;
        sA[d * 256 + g * 16 + 2 * p + 1] = v;
    }

    // Prefetch B tile 0
    for (int r = tid; r < 2048; r += 256) {
        int d = r >> 5, q = (r & 31) * 4;
        cp16(sB_base + (unsigned)(d * 128 + q) * 4u, g_CBt + d * KCB + q);
    }
    asm volatile("cp.async.commit_group;\n" ::: "memory");

    float mx[7];
    int bi[7];
#pragma unroll
    for (int r = 0; r < 7; r++) { mx[r] = -INFINITY; bi[r] = 0; }

    for (int kt = 0; kt < 128; kt++) {
        if (kt + 1 < 128) {
            unsigned dstb = sB_base + (unsigned)(((kt + 1) & 1) * 8192) * 4u;
            const float* srcb = g_CBt + (kt + 1) * 128;
            for (int r = tid; r < 2048; r += 256) {
                int d = r >> 5, q = (r & 31) * 4;
                cp16(dstb + (unsigned)(d * 128 + q) * 4u, srcb + d * KCB + q);
            }
            asm volatile("cp.async.commit_group;\n" ::: "memory");
            asm volatile("cp.async.wait_group 1;\n" ::: "memory");
        } else {
            asm volatile("cp.async.wait_group 0;\n" ::: "memory");
        }
        __syncthreads();
        const float* Bb = sB + (kt & 1) * 8192;

        unsigned long long acc[7][4];
#pragma unroll
        for (int r = 0; r < 7; r++)
#pragma unroll
            for (int p = 0; p < 4; p++) acc[r][p] = 0ULL;

#pragma unroll 8
        for (int d = 0; d < 64; d++) {
            const float* Ab = sA + d * 256 + ty * 16;
            ulonglong2 A0 = ((const ulonglong2*)Ab)[0];
            ulonglong2 A1 = ((const ulonglong2*)Ab)[1];
            ulonglong2 A2 = ((const ulonglong2*)Ab)[2];
            unsigned long long a6 = ((const unsigned long long*)Ab)[6];
            ulonglong2 B0 = *(const ulonglong2*)(Bb + d * 128 + tx * 4);
            ulonglong2 B1 = *(const ulonglong2*)(Bb + d * 128 + 64 + tx * 4);
            unsigned long long av[7] = {A0.x, A0.y, A1.x, A1.y, A2.x, A2.y, a6};
            unsigned long long bv[4] = {B0.x, B0.y, B1.x, B1.y};
#pragma unroll
            for (int r = 0; r < 7; r++)
#pragma unroll
                for (int p = 0; p < 4; p++)
                    fma2(acc[r][p], av[r], bv[p]);
        }

        // per-tile running argmax
        int kbase = kt * 128;
#pragma unroll
        for (int r = 0; r < 7; r++) {
#pragma unroll
            for (int p = 0; p < 4; p++) {
                float lo, hi;
                asm("mov.b64 {%0, %1}, %2;" : "=f"(lo), "=f"(hi) : "l"(acc[r][p]));
                int kk = kbase + ((p & 2) ? 64 : 0) + tx * 4 + ((p & 1) ? 2 : 0);
                if (lo > mx[r]) { mx[r] = lo; bi[r] = kk; }
                if (hi > mx[r]) { mx[r] = hi; bi[r] = kk + 1; }
            }
        }
        __syncthreads();   // before overwriting the buffer we just computed
    }

    // reduce argmax across the 16 tx-lanes sharing each row (tie -> lowest k)
#pragma unroll
    for (int r = 0; r < 7; r++) {
        float m = mx[r];
        int b = bi[r];
#pragma unroll
        for (int off = 8; off > 0; off >>= 1) {
            float om = __shfl_xor_sync(0xffffffffu, m, off, 16);
            int ob = __shfl_xor_sync(0xffffffffu, b, off, 16);
            if (om > m || (om == m && ob < b)) { m = om; b = ob; }
        }
        int rr = ty * 7 + r;
        if (tx == 0 && rr < cnt) g_idx[base + rr] = b;
    }
}

// ---------------------------------------------------------------- outputs
__global__ void gather_kernel(const float* __restrict__ cb, float* __restrict__ out) {
    int i = blockIdx.x * 256 + threadIdx.x;   // 524288 zhat elements
    if (i >= N_TOK * 256) return;
    int j = i & 255;
    int t = i >> 8;
    int idx = g_idx[t * 8 + (j & 7)];
    out[i] = cb[idx * 32 + (j >> 3)];          // zhat[t, d*8+c] = codebook[idx[t,c], d]
}

__global__ void final_small(float* __restrict__ out) {
    if (blockIdx.x == 0) {
        __shared__ float red[256];
        int j = threadIdx.x;
        float s = 0.0f;
        for (int i = j; i < N_TOK; i += 256) s += g_klpart[i];
        red[j] = s;
        __syncthreads();
        for (int st = 128; st > 0; st >>= 1) {
            if (j < st) red[j] += red[j + st];
            __syncthreads();
        }
        if (j == 0) out[524288] = red[0] * (1.4426f * 0.5f) / 16384.0f;
    } else {
        int i = (blockIdx.x - 1) * 256 + threadIdx.x;
        if (i < NROWS) out[524289 + i] = (float)g_idx[i];
    }
}

// ---------------------------------------------------------------- launch
extern "C" void kernel_launch(void* const* d_in, const int* in_sizes, int n_in,
                              void* d_out, int out_size) {
    const float* z  = (const float*)d_in[0];
    // d_in[1] (noise) is mathematically dead: forward zhat == codebook gather
    const float* cb = (const float*)d_in[2];
    float* out = (float*)d_out;

    cudaFuncSetAttribute(vq_kernel, cudaFuncAttributeMaxDynamicSharedMemorySize, 131072);

    prep_kernel<<<2048, 256>>>(z);
    cb_kernel<<<2048, 256>>>(cb);
    vq_kernel<<<NCTA, 256, 131072>>>();
    gather_kernel<<<2048, 256>>>(cb, out);
    final_small<<<65, 256>>>(out);
}

// round 8
// speedup vs baseline: 1.9221x; 1.0018x over previous
#include <cuda_runtime.h>
#include <math.h>

#define N_TOK 2048
#define NROWS 16384   // GEMM M rows (token, codebook-group)
#define KCB   16384   // codebook entries
#define NCTA  148     // one CTA per SM, balanced row ranges

// ---------------- persistent scratch (no allocs allowed) ----------------
__device__ float g_At[64 * NROWS];   // [f][n]: f<32 -> 0.5*(1-inv_var), f>=32 -> mu*inv_var
__device__ float g_CBt[64 * KCB];    // [f][k]: f<32 -> c^2, f>=32 -> c
__device__ float g_klpart[N_TOK];
__device__ int   g_idx[NROWS];

// ---------------------------------------------------------------- prep
__global__ void prep_kernel(const float* __restrict__ z) {
    int t = blockIdx.x;       // 2048 tokens
    int j = threadIdx.x;      // 256 features
    float mu = z[t * 512 + j];
    float lv = z[t * 512 + 256 + j];
    lv = fminf(fmaxf(lv, -30.0f), 20.0f);
    float var = expf(lv);
    float inv_var = 1.0f / var;
    int d = j >> 3, c = j & 7;
    int n = t * 8 + c;
    g_At[d * NROWS + n]        = 0.5f * (1.0f - inv_var);
    g_At[(d + 32) * NROWS + n] = mu * inv_var;

    float e = mu * mu + var - 1.0f - lv;   // kl partial (band coeffs sum to 1)
    __shared__ float red[256];
    red[j] = e;
    __syncthreads();
    for (int s = 128; s > 0; s >>= 1) {
        if (j < s) red[j] += red[j + s];
        __syncthreads();
    }
    if (j == 0) g_klpart[t] = red[0];
}

__global__ void cb_kernel(const float* __restrict__ cb) {
    int i = blockIdx.x * 256 + threadIdx.x;   // 524288
    if (i >= KCB * 32) return;
    int k = i >> 5, d = i & 31;
    float v = cb[i];
    g_CBt[d * KCB + k]        = v * v;
    g_CBt[(d + 32) * KCB + k] = v;
}

// ---------------------------------------------------------------- GEMM + argmax
__device__ __forceinline__ void cp16(unsigned dst, const void* src) {
    asm volatile("cp.async.cg.shared.global [%0], [%1], 16;\n" :: "r"(dst), "l"(src));
}
__device__ __forceinline__ void fma2(unsigned long long& d, unsigned long long a, unsigned long long b) {
    asm("fma.rn.f32x2 %0, %1, %2, %3;" : "=l"(d) : "l"(a), "l"(b), "l"(d));
}

// 148 CTAs x 256 threads (16x16). Each CTA owns rows [bid*16384/148, (bid+1)*16384/148)
// (110-111 rows), computes a padded 112-row tile: 7 rows/thread, BK=128 codebook
// entries per tile, 8 cols/thread as 4 f32x2 accumulators. A duplicated in smem so
// one LDS.128 yields two broadcast-ready (a,a) f32x2 operands.
__global__ __launch_bounds__(256, 1) void vq_kernel() {
    extern __shared__ float smem[];
    float* sA = smem;             // [64][256]: 16 ty-groups x (7 dup pairs + 2 pad floats)
    float* sB = smem + 64 * 256;  // [2][64][128] double-buffered
    int tid = threadIdx.x;
    int tx = tid & 15, ty = tid >> 4;
    int bid = blockIdx.x;
    int base = (int)(((long long)bid * NROWS) / NCTA);
    int cnt  = (int)(((long long)(bid + 1) * NROWS) / NCTA) - base;   // 110 or 111
    unsigned sB_base = (unsigned)__cvta_generic_to_shared(sB);

    // Load + duplicate A tile (112 rows, clamped reads for the pad rows)
    for (int i = tid; i < 64 * 112; i += 256) {
        int d = i / 112, r = i % 112;
        int n = base + r; if (n > NROWS - 1) n = NROWS - 1;
        float v = g_At[d * NROWS + n];
        int g = r / 7, p = r % 7;
        sA[d * 256 + g * 16 + 2 * p]     = v;
        sA[d * 256 + g * 16 + 2 * p + 1] = v;
    }

    // Prefetch B tile 0
    for (int r = tid; r < 2048; r += 256) {
        int d = r >> 5, q = (r & 31) * 4;
        cp16(sB_base + (unsigned)(d * 128 + q) * 4u, g_CBt + d * KCB + q);
    }
    asm volatile("cp.async.commit_group;\n" ::: "memory");

    float mx[7];
    int bi[7];
#pragma unroll
    for (int r = 0; r < 7; r++) { mx[r] = -INFINITY; bi[r] = 0; }

    for (int kt = 0; kt < 128; kt++) {
        if (kt + 1 < 128) {
            unsigned dstb = sB_base + (unsigned)(((kt + 1) & 1) * 8192) * 4u;
            const float* srcb = g_CBt + (kt + 1) * 128;
            for (int r = tid; r < 2048; r += 256) {
                int d = r >> 5, q = (r & 31) * 4;
                cp16(dstb + (unsigned)(d * 128 + q) * 4u, srcb + d * KCB + q);
            }
            asm volatile("cp.async.commit_group;\n" ::: "memory");
            asm volatile("cp.async.wait_group 1;\n" ::: "memory");
        } else {
            asm volatile("cp.async.wait_group 0;\n" ::: "memory");
        }
        __syncthreads();
        const float* Bb = sB + (kt & 1) * 8192;

        unsigned long long acc[7][4];
#pragma unroll
        for (int r = 0; r < 7; r++)
#pragma unroll
            for (int p = 0; p < 4; p++) acc[r][p] = 0ULL;

#pragma unroll 8
        for (int d = 0; d < 64; d++) {
            const float* Ab = sA + d * 256 + ty * 16;
            ulonglong2 A0 = ((const ulonglong2*)Ab)[0];
            ulonglong2 A1 = ((const ulonglong2*)Ab)[1];
            ulonglong2 A2 = ((const ulonglong2*)Ab)[2];
            unsigned long long a6 = ((const unsigned long long*)Ab)[6];
            ulonglong2 B0 = *(const ulonglong2*)(Bb + d * 128 + tx * 4);
            ulonglong2 B1 = *(const ulonglong2*)(Bb + d * 128 + 64 + tx * 4);
            unsigned long long av[7] = {A0.x, A0.y, A1.x, A1.y, A2.x, A2.y, a6};
            unsigned long long bv[4] = {B0.x, B0.y, B1.x, B1.y};
#pragma unroll
            for (int r = 0; r < 7; r++)
#pragma unroll
                for (int p = 0; p < 4; p++)
                    fma2(acc[r][p], av[r], bv[p]);
        }

        // per-tile running argmax
        int kbase = kt * 128;
#pragma unroll
        for (int r = 0; r < 7; r++) {
#pragma unroll
            for (int p = 0; p < 4; p++) {
                float lo, hi;
                asm("mov.b64 {%0, %1}, %2;" : "=f"(lo), "=f"(hi) : "l"(acc[r][p]));
                int kk = kbase + ((p & 2) ? 64 : 0) + tx * 4 + ((p & 1) ? 2 : 0);
                if (lo > mx[r]) { mx[r] = lo; bi[r] = kk; }
                if (hi > mx[r]) { mx[r] = hi; bi[r] = kk + 1; }
            }
        }
        __syncthreads();   // before overwriting the buffer we just computed
    }

    // reduce argmax across the 16 tx-lanes sharing each row (tie -> lowest k)
#pragma unroll
    for (int r = 0; r < 7; r++) {
        float m = mx[r];
        int b = bi[r];
#pragma unroll
        for (int off = 8; off > 0; off >>= 1) {
            float om = __shfl_xor_sync(0xffffffffu, m, off, 16);
            int ob = __shfl_xor_sync(0xffffffffu, b, off, 16);
            if (om > m || (om == m && ob < b)) { m = om; b = ob; }
        }
        int rr = ty * 7 + r;
        if (tx == 0 && rr < cnt) g_idx[base + rr] = b;
    }
}

// ---------------------------------------------------------------- outputs
__global__ void gather_kernel(const float* __restrict__ cb, float* __restrict__ out) {
    int i = blockIdx.x * 256 + threadIdx.x;   // 524288 zhat elements
    if (i >= N_TOK * 256) return;
    int j = i & 255;
    int t = i >> 8;
    int idx = g_idx[t * 8 + (j & 7)];
    out[i] = cb[idx * 32 + (j >> 3)];          // zhat[t, d*8+c] = codebook[idx[t,c], d]
}

__global__ void final_small(float* __restrict__ out) {
    if (blockIdx.x == 0) {
        __shared__ float red[256];
        int j = threadIdx.x;
        float s = 0.0f;
        for (int i = j; i < N_TOK; i += 256) s += g_klpart[i];
        red[j] = s;
        __syncthreads();
        for (int st = 128; st > 0; st >>= 1) {
            if (j < st) red[j] += red[j + st];
            __syncthreads();
        }
        if (j == 0) out[524288] = red[0] * (1.4426f * 0.5f) / 16384.0f;
    } else {
        int i = (blockIdx.x - 1) * 256 + threadIdx.x;
        if (i < NROWS) out[524289 + i] = (float)g_idx[i];
    }
}

// ---------------------------------------------------------------- launch
extern "C" void kernel_launch(void* const* d_in, const int* in_sizes, int n_in,
                              void* d_out, int out_size) {
    const float* z  = (const float*)d_in[0];
    // d_in[1] (noise) is mathematically dead: forward zhat == codebook gather
    const float* cb = (const float*)d_in[2];
    float* out = (float*)d_out;

    cudaFuncSetAttribute(vq_kernel, cudaFuncAttributeMaxDynamicSharedMemorySize, 131072);

    prep_kernel<<<2048, 256>>>(z);
    cb_kernel<<<2048, 256>>>(cb);
    vq_kernel<<<NCTA, 256, 131072>>>();
    gather_kernel<<<2048, 256>>>(cb, out);
    final_small<<<65, 256>>>(out);
}

// round 13
// speedup vs baseline: 2.1503x; 1.1187x over previous
#include <cuda_runtime.h>
#include <cuda_bf16.h>
#include <math.h>

#define N_TOK 2048
#define NROWS 16384
#define KCB   16384
#define NCTA  148
#define NF    82            // fp32 tiles of 128 cols: [0, 10496)
#define NHT   92            // tensor half-tiles of 64 cols: [10496, 16384)
#define TCOL0 (NF * 128)
#define TNC   (NHT * 64)

__device__ float g_At[64 * NROWS];
__device__ float g_CBt[64 * KCB];
__device__ __align__(16) __nv_bfloat16 g_Asp[NROWS * 128];
__device__ __align__(16) __nv_bfloat16 g_Bsp[KCB * 128];
__device__ float g_klpart[N_TOK];
__device__ int   g_idx[NROWS];
__device__ int   g_flagged[NROWS];
__device__ int   g_list[NROWS];
__device__ int   g_nflag;
__device__ unsigned long long g_rkey[NROWS];

// ---------------------------------------------------------------- prep (+A split)
__global__ void prep_kernel(const float* __restrict__ z) {
    int t = blockIdx.x, j = threadIdx.x;
    float mu = z[t * 512 + j];
    float lv = z[t * 512 + 256 + j];
    lv = fminf(fmaxf(lv, -30.0f), 20.0f);
    float var = expf(lv);
    float inv_var = 1.0f / var;
    int d = j >> 3, c = j & 7;
    int n = t * 8 + c;
    float a0 = 0.5f * (1.0f - inv_var);
    float a1 = mu * inv_var;
    g_At[d * NROWS + n]        = a0;
    g_At[(d + 32) * NROWS + n] = a1;
    __nv_bfloat16 h0 = __float2bfloat16(a0);
    __nv_bfloat16 h1 = __float2bfloat16(a1);
    g_Asp[n * 128 + d]        = h0;
    g_Asp[n * 128 + 64 + d]   = __float2bfloat16(a0 - __bfloat162float(h0));
    g_Asp[n * 128 + d + 32]   = h1;
    g_Asp[n * 128 + 96 + d]   = __float2bfloat16(a1 - __bfloat162float(h1));

    float e = mu * mu + var - 1.0f - lv;
    __shared__ float red[256];
    red[j] = e;
    __syncthreads();
    for (int s = 128; s > 0; s >>= 1) {
        if (j < s) red[j] += red[j + s];
        __syncthreads();
    }
    if (j == 0) g_klpart[t] = red[0];
}

__global__ void cb_kernel(const float* __restrict__ cb) {
    if (blockIdx.x == 0 && threadIdx.x == 0) g_nflag = 0;
    int i = blockIdx.x * 256 + threadIdx.x;
    if (i >= KCB * 32) return;
    int k = i >> 5, d = i & 31;
    float v = cb[i];
    float v2 = v * v;
    g_CBt[d * KCB + k]        = v2;
    g_CBt[(d + 32) * KCB + k] = v;
    __nv_bfloat16 h0 = __float2bfloat16(v2);
    __nv_bfloat16 h1 = __float2bfloat16(v);
    g_Bsp[k * 128 + d]        = h0;
    g_Bsp[k * 128 + 64 + d]   = __float2bfloat16(v2 - __bfloat162float(h0));
    g_Bsp[k * 128 + d + 32]   = h1;
    g_Bsp[k * 128 + 96 + d]   = __float2bfloat16(v - __bfloat162float(h1));
}

// ---------------------------------------------------------------- helpers
__device__ __forceinline__ void cp16(unsigned dst, const void* src) {
    asm volatile("cp.async.cg.shared.global [%0], [%1], 16;\n" :: "r"(dst), "l"(src));
}
__device__ __forceinline__ void fma2(unsigned long long& d, unsigned long long a, unsigned long long b) {
    asm("fma.rn.f32x2 %0, %1, %2, %3;" : "=l"(d) : "l"(a), "l"(b), "l"(d));
}
__device__ __forceinline__ void ldsm4(unsigned* d, unsigned addr) {
    asm volatile("ldmatrix.sync.aligned.m8n8.x4.shared.b16 {%0,%1,%2,%3}, [%4];"
                 : "=r"(d[0]), "=r"(d[1]), "=r"(d[2]), "=r"(d[3]) : "r"(addr));
}
__device__ __forceinline__ void mma16816(float* c, const unsigned* a, unsigned b0, unsigned b1) {
    asm volatile(
        "mma.sync.aligned.m16n8k16.row.col.f32.bf16.bf16.f32 "
        "{%0,%1,%2,%3}, {%4,%5,%6,%7}, {%8,%9}, {%0,%1,%2,%3};"
        : "+f"(c[0]), "+f"(c[1]), "+f"(c[2]), "+f"(c[3])
        : "r"(a[0]), "r"(a[1]), "r"(a[2]), "r"(a[3]), "r"(b0), "r"(b1));
}
__device__ __forceinline__ void bar_named(int id, int cnt) {
    asm volatile("bar.sync %0, %1;" :: "r"(id), "r"(cnt) : "memory");
}
__device__ __forceinline__ void top2_merge(float& mx, float& m2, int& bi,
                                           float omx, float om2, int obi) {
    float nm2 = fmaxf(fminf(mx, omx), fmaxf(m2, om2));
    if (omx > mx || (omx == mx && obi < bi)) { mx = omx; bi = obi; }
    m2 = nm2;
}
__device__ __forceinline__ unsigned long long packkey(float s, int idx) {
    unsigned u = __float_as_uint(s);
    u = (u & 0x80000000u) ? ~u : (u | 0x80000000u);
    return ((unsigned long long)u << 32) | (unsigned)(0xFFFFFFFFu - (unsigned)idx);
}

// smem layout (bytes)
#define OFF_AB 65536
#define OFF_BF 94208
#define OFF_BB 159744
#define OFF_MG 192512
#define SMEM_SZ 198784

// tensor sub-pass: m-tiles [MT0, MT0+MTN), one warp covers 16 cols of the half-tile
template <int MT0, int MTN>
__device__ __forceinline__ void tensor_pass(unsigned sab, unsigned sbbw, int lane,
                                            int colbase, float* smx, float* sm2, int* sbi) {
    int l15 = lane & 15, lhi = (lane >> 4) & 1;
    unsigned sx = (unsigned)(l15 & 7);
    float acc[MTN][2][4];
#pragma unroll
    for (int i = 0; i < MTN; i++)
#pragma unroll
        for (int n = 0; n < 2; n++)
#pragma unroll
            for (int r = 0; r < 4; r++) acc[i][n][r] = 0.0f;

    const int ASEL[3] = {0, 0, 1}, BSEL[3] = {0, 1, 0};
#pragma unroll
    for (int s = 0; s < 12; s++) {
        int term = s >> 2, kk = s & 3;
        int ak = ASEL[term] * 64 + kk * 16;
        int bk = BSEL[term] * 64 + kk * 16;
        unsigned bf[4];
        ldsm4(bf, sbbw + (unsigned)(l15 * 256) + ((((unsigned)(bk >> 3) + lhi) ^ sx) << 4));
#pragma unroll
        for (int i = 0; i < MTN; i++) {
            int mt = MT0 + i;
            unsigned af[4];
            ldsm4(af, sab + (unsigned)((mt * 16 + l15) * 256) + ((((unsigned)(ak >> 3) + lhi) ^ sx) << 4));
            mma16816(acc[i][0], af, bf[0], bf[2]);
            mma16816(acc[i][1], af, bf[1], bf[3]);
        }
    }
#pragma unroll
    for (int i = 0; i < MTN; i++) {
        int mt = MT0 + i;
#pragma unroll
        for (int h = 0; h < 2; h++) {
            int slot = mt * 2 + h;
#pragma unroll
            for (int ni = 0; ni < 2; ni++)
#pragma unroll
                for (int q = 0; q < 2; q++) {
                    float v = acc[i][ni][h * 2 + q];
                    int col = colbase + ni * 8 + q;
                    if (v > smx[slot]) { sm2[slot] = smx[slot]; smx[slot] = v; sbi[slot] = col; }
                    else if (v > sm2[slot]) sm2[slot] = v;
                }
        }
    }
}

// ---------------------------------------------------------------- hybrid VQ
__global__ __launch_bounds__(384, 1) void vq_hybrid() {
    extern __shared__ char smem[];
    unsigned s_u32 = (unsigned)__cvta_generic_to_shared(smem);
    float* sAf = (float*)smem;
    float* sBf = (float*)(smem + OFF_BF);
    float* fF   = (float*)(smem + OFF_MG);
    int*   fBi  = (int*)(smem + OFF_MG + 448);
    float* tMx  = (float*)(smem + OFF_MG + 896);
    float* tM2  = (float*)(smem + OFF_MG + 2688);
    int*   tBi  = (int*)(smem + OFF_MG + 4480);
    int tid = threadIdx.x;
    int bid = blockIdx.x;
    int base = (int)(((long long)bid * NROWS) / NCTA);
    int cnt  = (int)(((long long)(bid + 1) * NROWS) / NCTA) - base;

    // A tiles (fp32 dup + bf16 swizzled)
    for (int i = tid; i < 64 * 112; i += 384) {
        int d = i / 112, r = i % 112;
        int n = base + r; if (n > NROWS - 1) n = NROWS - 1;
        float v = g_At[d * NROWS + n];
        int g = r / 7, p = r % 7;
        sAf[d * 256 + g * 16 + 2 * p]     = v;
        sAf[d * 256 + g * 16 + 2 * p + 1] = v;
    }
    for (int i = tid; i < 112 * 16; i += 384) {
        int r = i >> 4, c = i & 15;
        int n = base + r; if (n > NROWS - 1) n = NROWS - 1;
        uint4 v = *(const uint4*)(g_Asp + (size_t)n * 128 + c * 8);
        *(uint4*)(smem + OFF_AB + r * 256 + ((c ^ (r & 7)) << 4)) = v;
    }
    __syncthreads();

    if (tid < 256) {
        // ============ fp32 group: 8 warps, cols [0, TCOL0) ============
        int tx = tid & 15, ty = tid >> 4;
        unsigned sBf_u = s_u32 + OFF_BF;
        for (int r = tid; r < 2048; r += 256) {
            int d = r >> 5, q = (r & 31) * 4;
            cp16(sBf_u + (unsigned)(d * 128 + q) * 4u, g_CBt + d * KCB + q);
        }
        asm volatile("cp.async.commit_group;\n" ::: "memory");

        float mx[7]; int bi[7];
#pragma unroll
        for (int r = 0; r < 7; r++) { mx[r] = -INFINITY; bi[r] = 0; }

        for (int kt = 0; kt < NF; kt++) {
            if (kt + 1 < NF) {
                unsigned dstb = sBf_u + (unsigned)(((kt + 1) & 1) * 8192) * 4u;
                const float* srcb = g_CBt + (kt + 1) * 128;
                for (int r = tid; r < 2048; r += 256) {
                    int d = r >> 5, q = (r & 31) * 4;
                    cp16(dstb + (unsigned)(d * 128 + q) * 4u, srcb + d * KCB + q);
                }
                asm volatile("cp.async.commit_group;\n" ::: "memory");
                asm volatile("cp.async.wait_group 1;\n" ::: "memory");
            } else {
                asm volatile("cp.async.wait_group 0;\n" ::: "memory");
            }
            bar_named(1, 256);
            const float* Bb = sBf + (kt & 1) * 8192;

            unsigned long long acc[7][4];
#pragma unroll
            for (int r = 0; r < 7; r++)
#pragma unroll
                for (int p = 0; p < 4; p++) acc[r][p] = 0ULL;

#pragma unroll 8
            for (int d = 0; d < 64; d++) {
                const float* Ab = sAf + d * 256 + ty * 16;
                ulonglong2 A0 = ((const ulonglong2*)Ab)[0];
                ulonglong2 A1 = ((const ulonglong2*)Ab)[1];
                ulonglong2 A2 = ((const ulonglong2*)Ab)[2];
                unsigned long long a6 = ((const unsigned long long*)Ab)[6];
                ulonglong2 B0 = *(const ulonglong2*)(Bb + d * 128 + tx * 4);
                ulonglong2 B1 = *(const ulonglong2*)(Bb + d * 128 + 64 + tx * 4);
                unsigned long long av[7] = {A0.x, A0.y, A1.x, A1.y, A2.x, A2.y, a6};
                unsigned long long bv[4] = {B0.x, B0.y, B1.x, B1.y};
#pragma unroll
                for (int r = 0; r < 7; r++)
#pragma unroll
                    for (int p = 0; p < 4; p++)
                        fma2(acc[r][p], av[r], bv[p]);
            }

            int kbase = kt * 128;
#pragma unroll
            for (int r = 0; r < 7; r++) {
#pragma unroll
                for (int p = 0; p < 4; p++) {
                    float lo, hi;
                    asm("mov.b64 {%0, %1}, %2;" : "=f"(lo), "=f"(hi) : "l"(acc[r][p]));
                    int kk = kbase + ((p & 2) ? 64 : 0) + tx * 4 + ((p & 1) ? 2 : 0);
                    if (lo > mx[r]) { mx[r] = lo; bi[r] = kk; }
                    if (hi > mx[r]) { mx[r] = hi; bi[r] = kk + 1; }
                }
            }
            bar_named(1, 256);
        }

#pragma unroll
        for (int r = 0; r < 7; r++) {
            float m = mx[r]; int b = bi[r];
#pragma unroll
            for (int off = 8; off > 0; off >>= 1) {
                float om = __shfl_xor_sync(0xffffffffu, m, off, 16);
                int   ob = __shfl_xor_sync(0xffffffffu, b, off, 16);
                if (om > m || (om == m && ob < b)) { m = om; b = ob; }
            }
            if (tx == 0) { fF[ty * 7 + r] = m; fBi[ty * 7 + r] = b; }
        }
    } else {
        // ============ tensor group: 4 warps, cols [TCOL0, 16384) ============
        int wtid = tid - 256;
        int w = wtid >> 5, lane = wtid & 31;
        unsigned sab = s_u32 + OFF_AB;
        unsigned sbb = s_u32 + OFF_BB;

        {
            const __nv_bfloat16* src = g_Bsp + (size_t)TCOL0 * 128;
#pragma unroll
            for (int t = 0; t < 8; t++) {
                int idx = wtid + t * 128;
                int r = idx >> 4, c = idx & 15;
                cp16(sbb + (unsigned)(r * 256) + ((c ^ (r & 7)) << 4), src + r * 128 + c * 8);
            }
            asm volatile("cp.async.commit_group;\n" ::: "memory");
        }

        float smx[14], sm2[14]; int sbi[14];
#pragma unroll
        for (int s = 0; s < 14; s++) { smx[s] = -INFINITY; sm2[s] = -INFINITY; sbi[s] = 0; }

        for (int ht = 0; ht < NHT; ht++) {
            if (ht + 1 < NHT) {
                const __nv_bfloat16* src = g_Bsp + (size_t)(TCOL0 + (ht + 1) * 64) * 128;
                unsigned dst = sbb + (unsigned)(((ht + 1) & 1) * 16384);
#pragma unroll
                for (int t = 0; t < 8; t++) {
                    int idx = wtid + t * 128;
                    int r = idx >> 4, c = idx & 15;
                    cp16(dst + (unsigned)(r * 256) + ((c ^ (r & 7)) << 4), src + r * 128 + c * 8);
                }
                asm volatile("cp.async.commit_group;\n" ::: "memory");
                asm volatile("cp.async.wait_group 1;\n" ::: "memory");
            } else {
                asm volatile("cp.async.wait_group 0;\n" ::: "memory");
            }
            bar_named(2, 128);
            unsigned sbbw = sbb + (unsigned)((ht & 1) * 16384) + (unsigned)(w * 16 * 256);
            int colbase = TCOL0 + ht * 64 + w * 16 + (lane & 3) * 2;
            tensor_pass<0, 4>(sab, sbbw, lane, colbase, smx, sm2, sbi);
            tensor_pass<4, 3>(sab, sbbw, lane, colbase, smx, sm2, sbi);
            bar_named(2, 128);
        }

#pragma unroll
        for (int s = 0; s < 14; s++) {
            float a_mx = smx[s], a_m2 = sm2[s]; int a_bi = sbi[s];
#pragma unroll
            for (int off = 1; off <= 2; off <<= 1) {
                float o_mx = __shfl_xor_sync(0xffffffffu, a_mx, off, 4);
                float o_m2 = __shfl_xor_sync(0xffffffffu, a_m2, off, 4);
                int   o_bi = __shfl_xor_sync(0xffffffffu, a_bi, off, 4);
                top2_merge(a_mx, a_m2, a_bi, o_mx, o_m2, o_bi);
            }
            if ((lane & 3) == 0) {
                int mt = s >> 1, h = s & 1;
                int row = mt * 16 + (lane >> 2) + 8 * h;
                tMx[w * 112 + row] = a_mx;
                tM2[w * 112 + row] = a_m2;
                tBi[w * 112 + row] = a_bi;
            }
        }
    }

    __syncthreads();

    if (tid < 112) {
        float F = fF[tid]; int Fb = fBi[tid];
        float T = -INFINITY, T2 = -INFINITY; int Tb = 0;
#pragma unroll
        for (int w = 0; w < 4; w++)
            top2_merge(T, T2, Tb, tMx[w * 112 + tid], tM2[w * 112 + tid], tBi[w * 112 + tid]);
        float e = 0.03f + 1e-3f * fmaxf(fabsf(F), fabsf(T));
        int win; int flag;
        if (F >= T + e) { win = Fb; flag = 0; }
        else if (T - e > F && (T - T2) > 2.0f * e) { win = Tb; flag = 0; }
        else { win = (F >= T) ? Fb : Tb; flag = 1; }
        if (tid < cnt) {
            int n = base + tid;
            g_idx[n] = win;
            g_flagged[n] = flag;
            if (flag) {
                g_rkey[n] = packkey(F, Fb);
                int p = atomicAdd(&g_nflag, 1);
                g_list[p] = n;
            }
        }
    }
}

// ---------------------------------------------------------------- exact rescue over tensor region
__global__ __launch_bounds__(256, 1) void rescue_kernel() {
    int bid = blockIdx.x;
    int c0 = TCOL0 + (int)(((long long)bid * TNC) / NCTA);
    int c1 = TCOL0 + (int)(((long long)(bid + 1) * TNC) / NCTA);
    int nc = c1 - c0;                       // 39 or 40
    __shared__ float sB[64 * 40];
    __shared__ int nf_s;
    int tid = threadIdx.x;
    if (tid == 0) nf_s = g_nflag;
    for (int i = tid; i < 64 * nc; i += 256) {
        int f = i / nc, c = i % nc;
        sB[f * 40 + c] = g_CBt[f * KCB + c0 + c];
    }
    __syncthreads();
    int nf = nf_s;
    for (int li = tid; li < nf; li += 256) {
        int n = g_list[li];
        float a[64];
#pragma unroll
        for (int f = 0; f < 64; f++) a[f] = g_At[f * NROWS + n];
        float mx = -INFINITY; int bi = 0;
        for (int c = 0; c < nc; c++) {
            float s = 0.0f;
#pragma unroll
            for (int f = 0; f < 64; f++) s += a[f] * sB[f * 40 + c];
            if (s > mx) { mx = s; bi = c0 + c; }
        }
        atomicMax(&g_rkey[n], packkey(mx, bi));
    }
}

__global__ void decode_kernel() {
    int n = blockIdx.x * 256 + threadIdx.x;
    if (n < NROWS && g_flagged[n])
        g_idx[n] = (int)(0xFFFFFFFFu - (unsigned)(g_rkey[n] & 0xFFFFFFFFULL));
}

// ---------------------------------------------------------------- outputs
__global__ void gather_kernel(const float* __restrict__ cb, float* __restrict__ out) {
    int i = blockIdx.x * 256 + threadIdx.x;
    if (i >= N_TOK * 256) return;
    int j = i & 255;
    int t = i >> 8;
    int idx = g_idx[t * 8 + (j & 7)];
    out[i] = cb[idx * 32 + (j >> 3)];
}

__global__ void final_small(float* __restrict__ out) {
    if (blockIdx.x == 0) {
        __shared__ float red[256];
        int j = threadIdx.x;
        float s = 0.0f;
        for (int i = j; i < N_TOK; i += 256) s += g_klpart[i];
        red[j] = s;
        __syncthreads();
        for (int st = 128; st > 0; st >>= 1) {
            if (j < st) red[j] += red[j + st];
            __syncthreads();
        }
        if (j == 0) out[524288] = red[0] * (1.4426f * 0.5f) / 16384.0f;
    } else {
        int i = (blockIdx.x - 1) * 256 + threadIdx.x;
        if (i < NROWS) out[524289 + i] = (float)g_idx[i];
    }
}

// ---------------------------------------------------------------- launch
extern "C" void kernel_launch(void* const* d_in, const int* in_sizes, int n_in,
                              void* d_out, int out_size) {
    const float* z  = (const float*)d_in[0];
    // d_in[1] (noise) mathematically dead: forward zhat == codebook gather
    const float* cb = (const float*)d_in[2];
    float* out = (float*)d_out;

    cudaFuncSetAttribute(vq_hybrid, cudaFuncAttributeMaxDynamicSharedMemorySize, SMEM_SZ);

    prep_kernel<<<2048, 256>>>(z);
    cb_kernel<<<2048, 256>>>(cb);
    vq_hybrid<<<NCTA, 384, SMEM_SZ>>>();
    rescue_kernel<<<NCTA, 256>>>();
    decode_kernel<<<64, 256>>>();
    gather_kernel<<<2048, 256>>>(cb, out);
    final_small<<<65, 256>>>(out);
}